// round 15
// baseline (speedup 1.0000x reference)
#include <cuda_runtime.h>
#include <cuda_fp16.h>
#include <math.h>
#include <stdint.h>

// ---------------- problem constants ----------------
#define S_LEN   2048
#define HID     7168
#define NH      32
#define Q_LORA  1536
#define KV_LORA 512
#define ROPE_D  64
#define CDIM    576
#define V_D     128
#define N12     (Q_LORA + CDIM)
#define MIN_MASKED (-10000.0f)

// ---------------- scratch ----------------
__device__ float  g_pre12[(size_t)S_LEN * N12];
__device__ float  g_qpe[(size_t)S_LEN * (NH * ROPE_D)];
__device__ __half g_xh   [(size_t)S_LEN * HID];
__device__ __half g_qah  [(size_t)S_LEN * Q_LORA];
__device__ __half g_kfullh[(size_t)S_LEN * CDIM];
__device__ __half g_qfullh[(size_t)NH * S_LEN * CDIM];
__device__ __half g_vkva [(size_t)NH * S_LEN * V_D];
__device__ __half g_attnh[(size_t)S_LEN * (NH * V_D)];
__device__ __half g_w12h[(size_t)HID * N12];
__device__ __half g_qrwh[(size_t)Q_LORA * (NH * ROPE_D)];
__device__ __half g_fqkh[(size_t)NH * Q_LORA * KV_LORA];
__device__ __half g_vuph[(size_t)NH * KV_LORA * V_D];
__device__ __half g_woh [(size_t)(NH * V_D) * HID];

// ---------------- helpers ----------------
__device__ __forceinline__ void mma16(float (&c)[4], const unsigned (&a)[4], const unsigned (&b)[2]) {
    asm volatile(
        "mma.sync.aligned.m16n8k16.row.col.f32.f16.f16.f32 "
        "{%0,%1,%2,%3}, {%4,%5,%6,%7}, {%8,%9}, {%0,%1,%2,%3};"
        : "+f"(c[0]), "+f"(c[1]), "+f"(c[2]), "+f"(c[3])
        : "r"(a[0]), "r"(a[1]), "r"(a[2]), "r"(a[3]), "r"(b[0]), "r"(b[1]));
}
__device__ __forceinline__ void ldsm4(unsigned &r0, unsigned &r1, unsigned &r2, unsigned &r3, uint32_t a) {
    asm volatile("ldmatrix.sync.aligned.m8n8.x4.shared.b16 {%0,%1,%2,%3}, [%4];"
                 : "=r"(r0), "=r"(r1), "=r"(r2), "=r"(r3) : "r"(a));
}
__device__ __forceinline__ void ldsm4t(unsigned &r0, unsigned &r1, unsigned &r2, unsigned &r3, uint32_t a) {
    asm volatile("ldmatrix.sync.aligned.m8n8.x4.trans.shared.b16 {%0,%1,%2,%3}, [%4];"
                 : "=r"(r0), "=r"(r1), "=r"(r2), "=r"(r3) : "r"(a));
}
__device__ __forceinline__ void cpasync16(uint32_t dst, const void* src, int srcsize) {
    asm volatile("cp.async.cg.shared.global [%0], [%1], 16, %2;"
                 :: "r"(dst), "l"(src), "r"(srcsize) : "memory");
}
__device__ __forceinline__ void cp_commit() { asm volatile("cp.async.commit_group;" ::: "memory"); }
template<int N> __device__ __forceinline__ void cp_wait() { asm volatile("cp.async.wait_group %0;" :: "n"(N) : "memory"); }
__device__ __forceinline__ uint32_t smem_addr32(const void* p) {
    uint32_t a;
    asm("{ .reg .u64 t; cvta.to.shared.u64 t, %1; cvt.u32.u64 %0, t; }" : "=r"(a) : "l"(p));
    return a;
}
__device__ __forceinline__ float ex2f(float x) {
    float y;
    asm("ex2.approx.f32 %0, %1;" : "=f"(y) : "f"(x));
    return y;
}

// ---------------- fp16 GEMM, 128x128 tile (used for vkva; B [K][N]) ----------------
#define STG_BYTES 32768

template<bool HALF_OUT>
__global__ void __launch_bounds__(256, 2)
gemm16_kernel(const __half* __restrict__ A, const __half* __restrict__ B, void* Cv,
              int M, int N, int K, int lda, int ldb, int ldc,
              long long sA, long long sB, long long sC,
              float alpha)
{
    extern __shared__ char smem[];
    const long long bz = blockIdx.z;
    A += bz * sA;  B += bz * sB;

    const int row0 = blockIdx.x * 128;
    const int col0 = blockIdx.y * 128;

    float*  Cf = (float*)Cv  + bz * sC;
    __half* Ch = (__half*)Cv + bz * sC;

    const int tid  = threadIdx.x;
    const int lane = tid & 31;
    const int wid  = tid >> 5;
    const int wm   = wid >> 2;
    const int wn   = wid & 3;
    const int g    = lane >> 2;
    const int tig  = lane & 3;

    uint32_t sbase = smem_addr32(smem);
    const int T = K >> 6;

    auto issue = [&](int t) {
        int k0 = t << 6;
        uint32_t st = sbase + (uint32_t)((t % 3) * STG_BYTES);
        #pragma unroll
        for (int e = 0; e < 4; e++) {
            int id = tid + e * 256;
            int r = id >> 3, c = id & 7;
            cpasync16(st + (uint32_t)(r * 128 + ((c ^ (r & 7)) * 16)),
                      A + (long long)(row0 + r) * lda + k0 + c * 8, 16);
        }
        #pragma unroll
        for (int e = 0; e < 4; e++) {
            int id = tid + e * 256;
            int k = id >> 4, c = id & 15;
            bool ok = (col0 + c * 8) < N;
            const __half* src = ok ? (B + (long long)(k0 + k) * ldb + col0 + c * 8) : B;
            cpasync16(st + 16384u + (uint32_t)(k * 256 + ((c ^ (k & 7)) * 16)), src, ok ? 16 : 0);
        }
        cp_commit();
    };

    float acc[4][4][4] = {};
    issue(0);
    if (1 < T) issue(1);

    const int rbA  = wm * 64 + ((lane >> 3) & 1) * 8 + (lane & 7);
    const int ksel = lane >> 4;

    for (int t = 0; t < T; t++) {
        if (t + 1 < T) cp_wait<1>();
        else           cp_wait<0>();
        __syncthreads();
        if (t + 2 < T) issue(t + 2);

        uint32_t stA = sbase + (uint32_t)((t % 3) * STG_BYTES);
        uint32_t stB = stA + 16384u;

        #pragma unroll
        for (int kk16 = 0; kk16 < 4; kk16++) {
            unsigned af[4][4], bf[4][2];
            int cA = kk16 * 2 + ksel;
            #pragma unroll
            for (int mi = 0; mi < 4; mi++) {
                int r = rbA + mi * 16;
                ldsm4(af[mi][0], af[mi][1], af[mi][2], af[mi][3],
                      stA + (uint32_t)(r * 128 + ((cA ^ (r & 7)) << 4)));
            }
            int kr = kk16 * 16 + ((lane >> 3) & 1) * 8 + (lane & 7);
            #pragma unroll
            for (int njp = 0; njp < 2; njp++) {
                int nch = wn * 4 + njp * 2 + (lane >> 4);
                ldsm4t(bf[2 * njp][0], bf[2 * njp][1], bf[2 * njp + 1][0], bf[2 * njp + 1][1],
                       stB + (uint32_t)(kr * 256 + ((nch ^ (kr & 7)) << 4)));
            }
            #pragma unroll
            for (int mi = 0; mi < 4; mi++)
                #pragma unroll
                for (int nj = 0; nj < 4; nj++)
                    mma16(acc[mi][nj], af[mi], bf[nj]);
        }
    }

    #pragma unroll
    for (int mi = 0; mi < 4; mi++) {
        int r = row0 + wm * 64 + mi * 16 + g;
        #pragma unroll
        for (int nj = 0; nj < 4; nj++) {
            int c = col0 + wn * 32 + nj * 8 + tig * 2;
            if (c < N) {
                float v0 = acc[mi][nj][0] * alpha;
                float v1 = acc[mi][nj][1] * alpha;
                float v2 = acc[mi][nj][2] * alpha;
                float v3 = acc[mi][nj][3] * alpha;
                if (HALF_OUT) {
                    *(__half2*)(Ch + (long long)r * ldc + c) =
                        __halves2half2(__float2half(v0), __float2half(v1));
                    *(__half2*)(Ch + (long long)(r + 8) * ldc + c) =
                        __halves2half2(__float2half(v2), __float2half(v3));
                } else {
                    *(float2*)(Cf + (long long)r * ldc + c)       = make_float2(v0, v1);
                    *(float2*)(Cf + (long long)(r + 8) * ldc + c) = make_float2(v2, v3);
                }
            }
        }
    }
}

// ---------------- fp16 GEMM, 128x256 WIDE tile (B [K][N]); warp tile 64x64 ----------------
// 1 CTA/SM (147KB smem). Same BK=64 / kk16 / t accumulation order as the 128-wide
// kernel -> per-element results bitwise identical.
#define WSTG_BYTES 49152

template<bool HALF_OUT>
__global__ void __launch_bounds__(256, 1)
gemm16w_kernel(const __half* __restrict__ A, const __half* __restrict__ B, void* Cv,
               int M, int N, int K, int lda, int ldb, int ldc,
               long long sA, long long sB, long long sC,
               float alpha)
{
    extern __shared__ char smem[];
    const long long bz = blockIdx.z;
    A += bz * sA;  B += bz * sB;

    const int row0 = blockIdx.x * 128;
    const int col0 = blockIdx.y * 256;

    float*  Cf = (float*)Cv  + bz * sC;
    __half* Ch = (__half*)Cv + bz * sC;

    const int tid  = threadIdx.x;
    const int lane = tid & 31;
    const int wid  = tid >> 5;
    const int wm   = wid >> 2;        // 0..1
    const int wn   = wid & 3;         // 0..3 (64 cols each)
    const int g    = lane >> 2;
    const int tig  = lane & 3;

    uint32_t sbase = smem_addr32(smem);
    const int T = K >> 6;

    auto issue = [&](int t) {
        int k0 = t << 6;
        uint32_t st = sbase + (uint32_t)((t % 3) * WSTG_BYTES);
        #pragma unroll
        for (int e = 0; e < 4; e++) {                 // A: 128 rows x 8 chunks (128B rows)
            int id = tid + e * 256;
            int r = id >> 3, c = id & 7;
            cpasync16(st + (uint32_t)(r * 128 + ((c ^ (r & 7)) * 16)),
                      A + (long long)(row0 + r) * lda + k0 + c * 8, 16);
        }
        #pragma unroll
        for (int e = 0; e < 8; e++) {                 // B: 64 rows x 32 chunks (512B rows)
            int id = tid + e * 256;
            int k = id >> 5, c = id & 31;
            bool ok = (col0 + c * 8) < N;
            const __half* src = ok ? (B + (long long)(k0 + k) * ldb + col0 + c * 8) : B;
            cpasync16(st + 16384u + (uint32_t)(k * 512 + ((c ^ (k & 7)) * 16)), src, ok ? 16 : 0);
        }
        cp_commit();
    };

    float acc[4][8][4] = {};
    issue(0);
    if (1 < T) issue(1);

    const int rbA  = wm * 64 + ((lane >> 3) & 1) * 8 + (lane & 7);
    const int ksel = lane >> 4;

    for (int t = 0; t < T; t++) {
        if (t + 1 < T) cp_wait<1>();
        else           cp_wait<0>();
        __syncthreads();
        if (t + 2 < T) issue(t + 2);

        uint32_t stA = sbase + (uint32_t)((t % 3) * WSTG_BYTES);
        uint32_t stB = stA + 16384u;

        #pragma unroll
        for (int kk16 = 0; kk16 < 4; kk16++) {
            unsigned af[4][4], bf[8][2];
            int cA = kk16 * 2 + ksel;
            #pragma unroll
            for (int mi = 0; mi < 4; mi++) {
                int r = rbA + mi * 16;
                ldsm4(af[mi][0], af[mi][1], af[mi][2], af[mi][3],
                      stA + (uint32_t)(r * 128 + ((cA ^ (r & 7)) << 4)));
            }
            int kr = kk16 * 16 + ((lane >> 3) & 1) * 8 + (lane & 7);
            #pragma unroll
            for (int njp = 0; njp < 4; njp++) {
                int nch = wn * 8 + njp * 2 + (lane >> 4);
                ldsm4t(bf[2 * njp][0], bf[2 * njp][1], bf[2 * njp + 1][0], bf[2 * njp + 1][1],
                       stB + (uint32_t)(kr * 512 + ((nch ^ (kr & 7)) << 4)));
            }
            #pragma unroll
            for (int mi = 0; mi < 4; mi++)
                #pragma unroll
                for (int nj = 0; nj < 8; nj++)
                    mma16(acc[mi][nj], af[mi], bf[nj]);
        }
    }

    #pragma unroll
    for (int mi = 0; mi < 4; mi++) {
        int r = row0 + wm * 64 + mi * 16 + g;
        #pragma unroll
        for (int nj = 0; nj < 8; nj++) {
            int c = col0 + wn * 64 + nj * 8 + tig * 2;
            if (c < N) {
                float v0 = acc[mi][nj][0] * alpha;
                float v1 = acc[mi][nj][1] * alpha;
                float v2 = acc[mi][nj][2] * alpha;
                float v3 = acc[mi][nj][3] * alpha;
                if (HALF_OUT) {
                    *(__half2*)(Ch + (long long)r * ldc + c) =
                        __halves2half2(__float2half(v0), __float2half(v1));
                    *(__half2*)(Ch + (long long)(r + 8) * ldc + c) =
                        __halves2half2(__float2half(v2), __float2half(v3));
                } else {
                    *(float2*)(Cf + (long long)r * ldc + c)       = make_float2(v0, v1);
                    *(float2*)(Cf + (long long)(r + 8) * ldc + c) = make_float2(v2, v3);
                }
            }
        }
    }
}

// ---------------- fused flash attention (unchanged from R13) ----------------
#define FL_SMEM 200704

__global__ void __launch_bounds__(256, 1)
flash_kernel(const __half* __restrict__ Qf, const __half* __restrict__ Kf,
             const __half* __restrict__ Vk, __half* __restrict__ attn,
             float scale)
{
    extern __shared__ char smem[];
    const int i = 15 - blockIdx.x;
    const int h = blockIdx.z;
    const int row0 = i * 128;
    const __half* Q = Qf + (size_t)h * S_LEN * CDIM;
    const __half* V = Vk + (size_t)h * S_LEN * V_D;
    const float scale2 = scale * 1.44269504088896f;

    const int tid  = threadIdx.x;
    const int lane = tid & 31;
    const int wid  = tid >> 5;
    const int wm   = wid >> 2;
    const int wn   = wid & 3;
    const int g    = lane >> 2;
    const int tig  = lane & 3;

    uint32_t sb = smem_addr32(smem);
    uint32_t Pb = sb + 98304u;
    uint32_t Vb = sb + 131072u;
    float* smax = (float*)(smem + 196608);
    float* ssum = (float*)(smem + 198656);

    float O[4][4][4] = {};
    float mst[4][2], lst[4][2];
    #pragma unroll
    for (int mi = 0; mi < 4; mi++) { mst[mi][0] = mst[mi][1] = -1e30f; lst[mi][0] = lst[mi][1] = 0.f; }

    const int rbA  = wm * 64 + ((lane >> 3) & 1) * 8 + (lane & 7);
    const int ksel = lane >> 4;

    auto issueV = [&](int jj) {
        uint32_t vb = Vb + (uint32_t)((jj & 1) * 32768);
        #pragma unroll
        for (int e = 0; e < 8; e++) {
            int id = tid + e * 256;
            int k = id >> 4, c = id & 15;
            uint32_t dst = vb + (uint32_t)((k >> 6) * 16384 + (k & 63) * 256 + ((c ^ (k & 7)) << 4));
            cpasync16(dst, V + (size_t)(jj * 128 + k) * V_D + c * 8, 16);
        }
        cp_commit();
    };
    auto issueS = [&](int jj, int t) {
        int k0 = t << 6;
        uint32_t st = sb + (uint32_t)((t % 3) * STG_BYTES);
        #pragma unroll
        for (int e = 0; e < 4; e++) {
            int id = tid + e * 256;
            int r = id >> 3, c = id & 7;
            cpasync16(st + (uint32_t)(r * 128 + ((c ^ (r & 7)) * 16)),
                      Q + (size_t)(row0 + r) * CDIM + k0 + c * 8, 16);
        }
        #pragma unroll
        for (int e = 0; e < 4; e++) {
            int id = tid + e * 256;
            int n = id >> 3, c = id & 7;
            cpasync16(st + 16384u + (uint32_t)(n * 128 + ((c ^ (n & 7)) * 16)),
                      Kf + (size_t)(jj * 128 + n) * CDIM + k0 + c * 8, 16);
        }
        cp_commit();
    };

    issueV(0);
    issueS(0, 0);
    issueS(0, 1);

    for (int j = 0; j <= i; j++) {
        float S[4][4][4] = {};
        for (int t = 0; t < 9; t++) {
            if (t + 1 < 9) cp_wait<1>();
            else           cp_wait<0>();
            __syncthreads();
            if (t + 2 < 9) issueS(j, t + 2);

            uint32_t stA = sb + (uint32_t)((t % 3) * STG_BYTES);
            uint32_t stB = stA + 16384u;
            #pragma unroll
            for (int kk16 = 0; kk16 < 4; kk16++) {
                unsigned af[4][4], bf[4][2];
                int cA = kk16 * 2 + ksel;
                #pragma unroll
                for (int mi = 0; mi < 4; mi++) {
                    int r = rbA + mi * 16;
                    ldsm4(af[mi][0], af[mi][1], af[mi][2], af[mi][3],
                          stA + (uint32_t)(r * 128 + ((cA ^ (r & 7)) << 4)));
                }
                int cB = kk16 * 2 + ((lane >> 3) & 1);
                #pragma unroll
                for (int njp = 0; njp < 2; njp++) {
                    int n = wn * 32 + njp * 16 + (lane >> 4) * 8 + (lane & 7);
                    ldsm4(bf[2 * njp][0], bf[2 * njp][1], bf[2 * njp + 1][0], bf[2 * njp + 1][1],
                          stB + (uint32_t)(n * 128 + ((cB ^ (n & 7)) << 4)));
                }
                #pragma unroll
                for (int mi = 0; mi < 4; mi++)
                    #pragma unroll
                    for (int nj = 0; nj < 4; nj++)
                        mma16(S[mi][nj], af[mi], bf[nj]);
            }
        }

        const bool diag = (j == i);
        float lm[4][2];
        #pragma unroll
        for (int mi = 0; mi < 4; mi++) { lm[mi][0] = lm[mi][1] = -1e30f; }
        #pragma unroll
        for (int mi = 0; mi < 4; mi++)
            #pragma unroll
            for (int nj = 0; nj < 4; nj++)
                #pragma unroll
                for (int c = 0; c < 4; c++) {
                    int hf = c >> 1;
                    int rl = wm * 64 + mi * 16 + g + hf * 8;
                    int cl = wn * 32 + nj * 8 + tig * 2 + (c & 1);
                    float s = S[mi][nj][c] * scale2;
                    if (diag && cl > rl) s = -1e30f;
                    S[mi][nj][c] = s;
                    lm[mi][hf] = fmaxf(lm[mi][hf], s);
                }
        #pragma unroll
        for (int mi = 0; mi < 4; mi++)
            #pragma unroll
            for (int hf = 0; hf < 2; hf++) {
                lm[mi][hf] = fmaxf(lm[mi][hf], __shfl_xor_sync(0xffffffffu, lm[mi][hf], 1));
                lm[mi][hf] = fmaxf(lm[mi][hf], __shfl_xor_sync(0xffffffffu, lm[mi][hf], 2));
            }
        if (tig == 0) {
            #pragma unroll
            for (int mi = 0; mi < 4; mi++)
                #pragma unroll
                for (int hf = 0; hf < 2; hf++)
                    smax[wn * 128 + wm * 64 + mi * 16 + g + hf * 8] = lm[mi][hf];
        }
        __syncthreads();

        float alpha_[4][2];
        #pragma unroll
        for (int mi = 0; mi < 4; mi++)
            #pragma unroll
            for (int hf = 0; hf < 2; hf++) {
                int rl = wm * 64 + mi * 16 + g + hf * 8;
                float mj = fmaxf(fmaxf(smax[rl], smax[128 + rl]),
                                 fmaxf(smax[256 + rl], smax[384 + rl]));
                float mn = fmaxf(mst[mi][hf], mj);
                float al = ex2f(mst[mi][hf] - mn);
                mst[mi][hf] = mn;
                lst[mi][hf] *= al;
                alpha_[mi][hf] = al;
            }
        #pragma unroll
        for (int mi = 0; mi < 4; mi++)
            #pragma unroll
            for (int nj = 0; nj < 4; nj++) {
                O[mi][nj][0] *= alpha_[mi][0]; O[mi][nj][1] *= alpha_[mi][0];
                O[mi][nj][2] *= alpha_[mi][1]; O[mi][nj][3] *= alpha_[mi][1];
            }

        float ls[4][2];
        #pragma unroll
        for (int mi = 0; mi < 4; mi++) { ls[mi][0] = ls[mi][1] = 0.f; }
        #pragma unroll
        for (int mi = 0; mi < 4; mi++)
            #pragma unroll
            for (int nj = 0; nj < 4; nj++) {
                #pragma unroll
                for (int c = 0; c < 4; c++) {
                    int hf = c >> 1;
                    float p = ex2f(S[mi][nj][c] - mst[mi][hf]);
                    S[mi][nj][c] = p;
                    ls[mi][hf] += p;
                }
                int cc = wn * 32 + nj * 8 + tig * 2;
                uint32_t hb  = (uint32_t)(cc >> 6) * 16384u;
                int ccc = cc & 63;
                int r1 = wm * 64 + mi * 16 + g;
                uint32_t a1 = Pb + hb + (uint32_t)(r1 * 128 + ((((ccc >> 3) ^ (r1 & 7))) << 4) + (ccc & 7) * 2);
                int r2 = r1 + 8;
                uint32_t a2 = Pb + hb + (uint32_t)(r2 * 128 + ((((ccc >> 3) ^ (r2 & 7))) << 4) + (ccc & 7) * 2);
                __half2 v1 = __floats2half2_rn(S[mi][nj][0] * 512.f, S[mi][nj][1] * 512.f);
                __half2 v2 = __floats2half2_rn(S[mi][nj][2] * 512.f, S[mi][nj][3] * 512.f);
                *(__half2*)(smem + (a1 - sb)) = v1;
                *(__half2*)(smem + (a2 - sb)) = v2;
            }
        #pragma unroll
        for (int mi = 0; mi < 4; mi++)
            #pragma unroll
            for (int hf = 0; hf < 2; hf++) {
                ls[mi][hf] += __shfl_xor_sync(0xffffffffu, ls[mi][hf], 1);
                ls[mi][hf] += __shfl_xor_sync(0xffffffffu, ls[mi][hf], 2);
            }
        if (tig == 0) {
            #pragma unroll
            for (int mi = 0; mi < 4; mi++)
                #pragma unroll
                for (int hf = 0; hf < 2; hf++)
                    ssum[wn * 128 + wm * 64 + mi * 16 + g + hf * 8] = ls[mi][hf];
        }
        __syncthreads();

        #pragma unroll
        for (int mi = 0; mi < 4; mi++)
            #pragma unroll
            for (int hf = 0; hf < 2; hf++) {
                int rl = wm * 64 + mi * 16 + g + hf * 8;
                lst[mi][hf] += ssum[rl] + ssum[128 + rl] + ssum[256 + rl] + ssum[384 + rl];
            }

        if (j < i) {
            issueV(j + 1);
            issueS(j + 1, 0);
            issueS(j + 1, 1);
        }

        uint32_t Vcur = Vb + (uint32_t)((j & 1) * 32768);
        #pragma unroll
        for (int kk64 = 0; kk64 < 2; kk64++) {
            uint32_t stA = Pb + (uint32_t)(kk64 * 16384);
            uint32_t stV = Vcur + (uint32_t)(kk64 * 16384);
            #pragma unroll
            for (int kk16 = 0; kk16 < 4; kk16++) {
                unsigned af[4][4], bf[4][2];
                int cA = kk16 * 2 + ksel;
                #pragma unroll
                for (int mi = 0; mi < 4; mi++) {
                    int r = rbA + mi * 16;
                    ldsm4(af[mi][0], af[mi][1], af[mi][2], af[mi][3],
                          stA + (uint32_t)(r * 128 + ((cA ^ (r & 7)) << 4)));
                }
                int kr = kk16 * 16 + ((lane >> 3) & 1) * 8 + (lane & 7);
                #pragma unroll
                for (int njp = 0; njp < 2; njp++) {
                    int nch = wn * 4 + njp * 2 + (lane >> 4);
                    ldsm4t(bf[2 * njp][0], bf[2 * njp][1], bf[2 * njp + 1][0], bf[2 * njp + 1][1],
                           stV + (uint32_t)(kr * 256 + ((nch ^ (kr & 7)) << 4)));
                }
                #pragma unroll
                for (int mi = 0; mi < 4; mi++)
                    #pragma unroll
                    for (int nj = 0; nj < 4; nj++)
                        mma16(O[mi][nj], af[mi], bf[nj]);
            }
        }
    }

    #pragma unroll
    for (int mi = 0; mi < 4; mi++) {
        float inv0 = 1.0f / (512.0f * lst[mi][0]);
        float inv1 = 1.0f / (512.0f * lst[mi][1]);
        int r = row0 + wm * 64 + mi * 16 + g;
        #pragma unroll
        for (int nj = 0; nj < 4; nj++) {
            int c = h * V_D + wn * 32 + nj * 8 + tig * 2;
            *(__half2*)(attn + (size_t)r * (NH * V_D) + c) =
                __floats2half2_rn(O[mi][nj][0] * inv0, O[mi][nj][1] * inv0);
            *(__half2*)(attn + (size_t)(r + 8) * (NH * V_D) + c) =
                __floats2half2_rn(O[mi][nj][2] * inv1, O[mi][nj][3] * inv1);
        }
    }
}

// ---------------- prepass converts (one uint4 per thread, full grid) ----------------
__global__ void convert_f2h_kernel(const float4* __restrict__ src, uint4* __restrict__ dst, int n8)
{
    int i = blockIdx.x * blockDim.x + threadIdx.x;
    if (i < n8) {
        float4 a = src[2 * i], b = src[2 * i + 1];
        __half2 h0 = __floats2half2_rn(a.x, a.y);
        __half2 h1 = __floats2half2_rn(a.z, a.w);
        __half2 h2 = __floats2half2_rn(b.x, b.y);
        __half2 h3 = __floats2half2_rn(b.z, b.w);
        uint4 o;
        o.x = *(unsigned*)&h0; o.y = *(unsigned*)&h1;
        o.z = *(unsigned*)&h2; o.w = *(unsigned*)&h3;
        dst[i] = o;
    }
}
__global__ void pack_f2h_kernel(const float* __restrict__ src, __half* __restrict__ dst,
                                int C, int ldd, int off)
{
    int c4 = blockIdx.x * blockDim.x + threadIdx.x;
    int r  = blockIdx.y;
    if (c4 < C / 4) {
        float4 v = *(const float4*)(src + (long long)r * C + 4 * c4);
        __half2 h0 = __floats2half2_rn(v.x, v.y);
        __half2 h1 = __floats2half2_rn(v.z, v.w);
        uint2 o; o.x = *(unsigned*)&h0; o.y = *(unsigned*)&h1;
        *(uint2*)(dst + (long long)r * ldd + off + 4 * c4) = o;
    }
}

// ---------------- rmsnorm / rope kernels (unchanged) ----------------
__global__ void kva_rms_rope_kernel(const float* __restrict__ pre12,
                                    const float* __restrict__ kv_ln,
                                    const int*   __restrict__ pos_ids,
                                    __half* __restrict__ kfull)
{
    int s = blockIdx.x;
    const float* x = pre12 + (long long)s * N12 + Q_LORA;
    __half* out = kfull + (long long)s * CDIM;

    __shared__ float red[128];
    float ss = 0.0f;
    for (int i = threadIdx.x; i < KV_LORA; i += 128) { float v = x[i]; ss += v * v; }
    red[threadIdx.x] = ss; __syncthreads();
    for (int st = 64; st > 0; st >>= 1) {
        if (threadIdx.x < st) red[threadIdx.x] += red[threadIdx.x + st];
        __syncthreads();
    }
    float scale = rsqrtf(red[0] / (float)KV_LORA + 1e-6f);

    for (int i = threadIdx.x; i < KV_LORA; i += 128)
        out[i] = __float2half(x[i] * scale * kv_ln[i]);

    if (threadIdx.x < ROPE_D / 2) {
        int j = threadIdx.x;
        float pos  = (float)pos_ids[s];
        float invf = powf(10000.0f, -(float)(2 * j) / (float)ROPE_D);
        float ang  = pos * invf;
        float c = cosf(ang), sn = sinf(ang);
        float x0 = x[KV_LORA + 2 * j];
        float x1 = x[KV_LORA + 2 * j + 1];
        out[KV_LORA + j]              = __float2half(x0 * c - x1 * sn);
        out[KV_LORA + ROPE_D / 2 + j] = __float2half(x1 * c + x0 * sn);
    }
}
__global__ void qa_rms_kernel(const float* __restrict__ pre12,
                              const float* __restrict__ w,
                              __half* __restrict__ outp)
{
    int s = blockIdx.x;
    const float* x = pre12 + (long long)s * N12;
    __half* o = outp + (long long)s * Q_LORA;

    __shared__ float red[256];
    float ss = 0.0f;
    for (int i = threadIdx.x; i < Q_LORA; i += 256) { float v = x[i]; ss += v * v; }
    red[threadIdx.x] = ss; __syncthreads();
    for (int st = 128; st > 0; st >>= 1) {
        if (threadIdx.x < st) red[threadIdx.x] += red[threadIdx.x + st];
        __syncthreads();
    }
    float scale = rsqrtf(red[0] / (float)Q_LORA + 1e-6f);
    for (int i = threadIdx.x; i < Q_LORA; i += 256)
        o[i] = __float2half(x[i] * scale * w[i]);
}
__global__ void rope_q_kernel(const float* __restrict__ qpe,
                              const int*   __restrict__ pos_ids,
                              __half* __restrict__ qfull)
{
    int s = blockIdx.x;
    int h = blockIdx.y * 8 + (threadIdx.x >> 5);
    int j = threadIdx.x & 31;
    float pos  = (float)pos_ids[s];
    float invf = powf(10000.0f, -(float)(2 * j) / (float)ROPE_D);
    float ang  = pos * invf;
    float c = cosf(ang), sn = sinf(ang);
    const float* x = qpe + (long long)s * (NH * ROPE_D) + h * ROPE_D;
    float x0 = x[2 * j], x1 = x[2 * j + 1];
    __half* out = qfull + ((long long)h * S_LEN + s) * CDIM + KV_LORA;
    out[j]              = __float2half(x0 * c - x1 * sn);
    out[j + ROPE_D / 2] = __float2half(x1 * c + x0 * sn);
}

// ---------------- host launchers ----------------
template<bool HALF_OUT>
static void launch_gemm16(const __half* A, const __half* B, void* C,
                          int M, int N, int K, int lda, int ldb, int ldc,
                          long long sA, long long sB, long long sC,
                          int batch, float alpha)
{
    dim3 grid(M / 128, (N + 127) / 128, batch);
    cudaFuncSetAttribute(gemm16_kernel<HALF_OUT>, cudaFuncAttributeMaxDynamicSharedMemorySize, 3 * STG_BYTES);
    gemm16_kernel<HALF_OUT><<<grid, 256, 3 * STG_BYTES>>>(A, B, C, M, N, K, lda, ldb, ldc, sA, sB, sC, alpha);
}
template<bool HALF_OUT>
static void launch_gemm16w(const __half* A, const __half* B, void* C,
                           int M, int N, int K, int lda, int ldb, int ldc,
                           long long sA, long long sB, long long sC,
                           int batch, float alpha)
{
    dim3 grid(M / 128, (N + 255) / 256, batch);
    cudaFuncSetAttribute(gemm16w_kernel<HALF_OUT>, cudaFuncAttributeMaxDynamicSharedMemorySize, 3 * WSTG_BYTES);
    gemm16w_kernel<HALF_OUT><<<grid, 256, 3 * WSTG_BYTES>>>(A, B, C, M, N, K, lda, ldb, ldc, sA, sB, sC, alpha);
}
static void launch_convert(const float* src, __half* dst, size_t n)
{
    int n8 = (int)(n / 8);
    int blocks = (n8 + 255) / 256;
    convert_f2h_kernel<<<blocks, 256>>>((const float4*)src, (uint4*)dst, n8);
}

extern "C" void kernel_launch(void* const* d_in, const int* in_sizes, int n_in,
                              void* d_out, int out_size)
{
    (void)in_sizes; (void)n_in; (void)out_size;
    const float* X        = (const float*)d_in[0];
    const int*   pos      = (const int*)d_in[2];
    const float* W_kv_a   = (const float*)d_in[3];
    const float* W_q_a    = (const float*)d_in[4];
    const float* q_ln     = (const float*)d_in[5];
    const float* kv_ln    = (const float*)d_in[6];
    const float* q_rope_w = (const float*)d_in[7];
    const float* fusedqk  = (const float*)d_in[8];
    const float* v_up     = (const float*)d_in[9];
    const float* W_o      = (const float*)d_in[10];
    float* out = (float*)d_out;

    float  *pre12, *qpe;
    __half *xh, *qah, *kfullh, *qfullh, *vkva, *attnh;
    __half *w12h, *qrwh, *fqkh, *vuph, *woh;
    cudaGetSymbolAddress((void**)&pre12,  g_pre12);
    cudaGetSymbolAddress((void**)&qpe,    g_qpe);
    cudaGetSymbolAddress((void**)&xh,     g_xh);
    cudaGetSymbolAddress((void**)&qah,    g_qah);
    cudaGetSymbolAddress((void**)&kfullh, g_kfullh);
    cudaGetSymbolAddress((void**)&qfullh, g_qfullh);
    cudaGetSymbolAddress((void**)&vkva,   g_vkva);
    cudaGetSymbolAddress((void**)&attnh,  g_attnh);
    cudaGetSymbolAddress((void**)&w12h,   g_w12h);
    cudaGetSymbolAddress((void**)&qrwh,   g_qrwh);
    cudaGetSymbolAddress((void**)&fqkh,   g_fqkh);
    cudaGetSymbolAddress((void**)&vuph,   g_vuph);
    cudaGetSymbolAddress((void**)&woh,    g_woh);

    const float scale = 1.0f / sqrtf(192.0f);

    // 0) prepass converts
    launch_convert(X,        xh,   (size_t)S_LEN * HID);
    pack_f2h_kernel<<<dim3((Q_LORA / 4 + 255) / 256, HID), 256>>>(W_q_a,  w12h, Q_LORA, N12, 0);
    pack_f2h_kernel<<<dim3((CDIM   / 4 + 255) / 256, HID), 256>>>(W_kv_a, w12h, CDIM,   N12, Q_LORA);
    launch_convert(q_rope_w, qrwh, (size_t)Q_LORA * (NH * ROPE_D));
    launch_convert(fusedqk,  fqkh, (size_t)NH * Q_LORA * KV_LORA);
    launch_convert(v_up,     vuph, (size_t)NH * KV_LORA * V_D);
    launch_convert(W_o,      woh,  (size_t)(NH * V_D) * HID);

    // 1+2) pre12 = X @ [W_q | W_kv]   (wide)
    launch_gemm16w<false>(xh, w12h, pre12, S_LEN, N12, HID,
                          HID, N12, N12, 0, 0, 0, 1, 1.0f);
    // 3) kfullh
    kva_rms_rope_kernel<<<S_LEN, 128>>>(pre12, kv_ln, pos, kfullh);
    // 3b) vkva[h] = kva @ v_up[h]   (narrow, N=128)
    launch_gemm16<true>(kfullh, vuph, vkva, S_LEN, V_D, KV_LORA,
                        CDIM, V_D, V_D,
                        0, (long long)KV_LORA * V_D, (long long)S_LEN * V_D,
                        NH, 1.0f);
    // 4) qah
    qa_rms_kernel<<<S_LEN, 256>>>(pre12, q_ln, qah);
    // 5) qpe = qa @ q_rope_w   (wide)
    launch_gemm16w<false>(qah, qrwh, qpe, S_LEN, NH * ROPE_D, Q_LORA,
                          Q_LORA, NH * ROPE_D, NH * ROPE_D, 0, 0, 0, 1, 1.0f);
    // 6) rope(q_pe)
    rope_q_kernel<<<dim3(S_LEN, NH / 8), 256>>>(qpe, pos, qfullh);
    // 7) dq = qa @ fusedqk[h]   (wide, batched)
    launch_gemm16w<true>(qah, fqkh, qfullh, S_LEN, KV_LORA, Q_LORA,
                         Q_LORA, KV_LORA, CDIM,
                         0, (long long)Q_LORA * KV_LORA, (long long)S_LEN * CDIM,
                         NH, 1.0f);
    // 8-10) fused flash attention -> attnh
    {
        cudaFuncSetAttribute(flash_kernel, cudaFuncAttributeMaxDynamicSharedMemorySize, FL_SMEM);
        dim3 grid(S_LEN / 128, 1, NH);
        flash_kernel<<<grid, 256, FL_SMEM>>>(qfullh, kfullh, vkva, attnh, scale);
    }
    // 12) out = attn @ W_o   (wide)
    launch_gemm16w<false>(attnh, woh, out, S_LEN, HID, NH * V_D,
                          NH * V_D, HID, HID, 0, 0, 0, 1, 1.0f);
}

// round 16
// speedup vs baseline: 1.0453x; 1.0453x over previous
#include <cuda_runtime.h>
#include <cuda_fp16.h>
#include <math.h>
#include <stdint.h>

// ---------------- problem constants ----------------
#define S_LEN   2048
#define HID     7168
#define NH      32
#define Q_LORA  1536
#define KV_LORA 512
#define ROPE_D  64
#define CDIM    576
#define V_D     128
#define N12     (Q_LORA + CDIM)
#define MIN_MASKED (-10000.0f)

// ---------------- scratch ----------------
__device__ float  g_pre12[(size_t)S_LEN * N12];
__device__ __half g_xh   [(size_t)S_LEN * HID];
__device__ __half g_qah  [(size_t)S_LEN * Q_LORA];
__device__ __half g_kfullh[(size_t)S_LEN * CDIM];
__device__ __half g_qfullh[(size_t)NH * S_LEN * CDIM];
__device__ __half g_vkva [(size_t)NH * S_LEN * V_D];
__device__ __half g_attnh[(size_t)S_LEN * (NH * V_D)];
__device__ __half g_w12h[(size_t)HID * N12];
__device__ __half g_qrwh[(size_t)Q_LORA * (NH * ROPE_D)];
__device__ __half g_fqkh[(size_t)NH * Q_LORA * KV_LORA];
__device__ __half g_vuph[(size_t)NH * KV_LORA * V_D];
__device__ __half g_woh [(size_t)(NH * V_D) * HID];

// ---------------- helpers ----------------
__device__ __forceinline__ void mma16(float (&c)[4], const unsigned (&a)[4], const unsigned (&b)[2]) {
    asm volatile(
        "mma.sync.aligned.m16n8k16.row.col.f32.f16.f16.f32 "
        "{%0,%1,%2,%3}, {%4,%5,%6,%7}, {%8,%9}, {%0,%1,%2,%3};"
        : "+f"(c[0]), "+f"(c[1]), "+f"(c[2]), "+f"(c[3])
        : "r"(a[0]), "r"(a[1]), "r"(a[2]), "r"(a[3]), "r"(b[0]), "r"(b[1]));
}
__device__ __forceinline__ void ldsm4(unsigned &r0, unsigned &r1, unsigned &r2, unsigned &r3, uint32_t a) {
    asm volatile("ldmatrix.sync.aligned.m8n8.x4.shared.b16 {%0,%1,%2,%3}, [%4];"
                 : "=r"(r0), "=r"(r1), "=r"(r2), "=r"(r3) : "r"(a));
}
__device__ __forceinline__ void ldsm4t(unsigned &r0, unsigned &r1, unsigned &r2, unsigned &r3, uint32_t a) {
    asm volatile("ldmatrix.sync.aligned.m8n8.x4.trans.shared.b16 {%0,%1,%2,%3}, [%4];"
                 : "=r"(r0), "=r"(r1), "=r"(r2), "=r"(r3) : "r"(a));
}
__device__ __forceinline__ void cpasync16(uint32_t dst, const void* src, int srcsize) {
    asm volatile("cp.async.cg.shared.global [%0], [%1], 16, %2;"
                 :: "r"(dst), "l"(src), "r"(srcsize) : "memory");
}
__device__ __forceinline__ void cp_commit() { asm volatile("cp.async.commit_group;" ::: "memory"); }
template<int N> __device__ __forceinline__ void cp_wait() { asm volatile("cp.async.wait_group %0;" :: "n"(N) : "memory"); }
__device__ __forceinline__ uint32_t smem_addr32(const void* p) {
    uint32_t a;
    asm("{ .reg .u64 t; cvta.to.shared.u64 t, %1; cvt.u32.u64 %0, t; }" : "=r"(a) : "l"(p));
    return a;
}
__device__ __forceinline__ float ex2f(float x) {
    float y;
    asm("ex2.approx.f32 %0, %1;" : "=f"(y) : "f"(x));
    return y;
}

// ---------------- fp16 GEMM, 128x128 tile, B [K][N], 3-stage (R13 engine) ----------------
// OMODE 0: f32 out; 1: f16 out; 2: RoPE epilogue -> ropeDst (qpe GEMM; C never stored)
#define STG_BYTES 32768

template<int OMODE>
__global__ void __launch_bounds__(256, 2)
gemm16_kernel(const __half* __restrict__ A, const __half* __restrict__ B, void* Cv,
              int M, int N, int K, int lda, int ldb, int ldc,
              long long sA, long long sB, long long sC,
              float alpha, const int* __restrict__ pos, __half* __restrict__ ropeDst)
{
    extern __shared__ char smem[];
    const long long bz = blockIdx.z;
    A += bz * sA;  B += bz * sB;

    const int row0 = blockIdx.x * 128;
    const int col0 = blockIdx.y * 128;

    float*  Cf = (float*)Cv  + bz * sC;
    __half* Ch = (__half*)Cv + bz * sC;

    const int tid  = threadIdx.x;
    const int lane = tid & 31;
    const int wid  = tid >> 5;
    const int wm   = wid >> 2;
    const int wn   = wid & 3;
    const int g    = lane >> 2;
    const int tig  = lane & 3;

    uint32_t sbase = smem_addr32(smem);
    const int T = K >> 6;

    auto issue = [&](int t) {
        int k0 = t << 6;
        uint32_t st = sbase + (uint32_t)((t % 3) * STG_BYTES);
        #pragma unroll
        for (int e = 0; e < 4; e++) {
            int id = tid + e * 256;
            int r = id >> 3, c = id & 7;
            cpasync16(st + (uint32_t)(r * 128 + ((c ^ (r & 7)) * 16)),
                      A + (long long)(row0 + r) * lda + k0 + c * 8, 16);
        }
        #pragma unroll
        for (int e = 0; e < 4; e++) {
            int id = tid + e * 256;
            int k = id >> 4, c = id & 15;
            bool ok = (col0 + c * 8) < N;
            const __half* src = ok ? (B + (long long)(k0 + k) * ldb + col0 + c * 8) : B;
            cpasync16(st + 16384u + (uint32_t)(k * 256 + ((c ^ (k & 7)) * 16)), src, ok ? 16 : 0);
        }
        cp_commit();
    };

    float acc[4][4][4] = {};
    issue(0);
    if (1 < T) issue(1);

    const int rbA  = wm * 64 + ((lane >> 3) & 1) * 8 + (lane & 7);
    const int ksel = lane >> 4;

    for (int t = 0; t < T; t++) {
        if (t + 1 < T) cp_wait<1>();
        else           cp_wait<0>();
        __syncthreads();
        if (t + 2 < T) issue(t + 2);

        uint32_t stA = sbase + (uint32_t)((t % 3) * STG_BYTES);
        uint32_t stB = stA + 16384u;

        #pragma unroll
        for (int kk16 = 0; kk16 < 4; kk16++) {
            unsigned af[4][4], bf[4][2];
            int cA = kk16 * 2 + ksel;
            #pragma unroll
            for (int mi = 0; mi < 4; mi++) {
                int r = rbA + mi * 16;
                ldsm4(af[mi][0], af[mi][1], af[mi][2], af[mi][3],
                      stA + (uint32_t)(r * 128 + ((cA ^ (r & 7)) << 4)));
            }
            int kr = kk16 * 16 + ((lane >> 3) & 1) * 8 + (lane & 7);
            #pragma unroll
            for (int njp = 0; njp < 2; njp++) {
                int nch = wn * 4 + njp * 2 + (lane >> 4);
                ldsm4t(bf[2 * njp][0], bf[2 * njp][1], bf[2 * njp + 1][0], bf[2 * njp + 1][1],
                       stB + (uint32_t)(kr * 256 + ((nch ^ (kr & 7)) << 4)));
            }
            #pragma unroll
            for (int mi = 0; mi < 4; mi++)
                #pragma unroll
                for (int nj = 0; nj < 4; nj++)
                    mma16(acc[mi][nj], af[mi], bf[nj]);
        }
    }

    #pragma unroll
    for (int mi = 0; mi < 4; mi++) {
        int r = row0 + wm * 64 + mi * 16 + g;
        #pragma unroll
        for (int nj = 0; nj < 4; nj++) {
            int c = col0 + wn * 32 + nj * 8 + tig * 2;
            if (c < N) {
                float v0 = acc[mi][nj][0] * alpha;
                float v1 = acc[mi][nj][1] * alpha;
                float v2 = acc[mi][nj][2] * alpha;
                float v3 = acc[mi][nj][3] * alpha;
                if (OMODE == 0) {
                    *(float2*)(Cf + (long long)r * ldc + c)       = make_float2(v0, v1);
                    *(float2*)(Cf + (long long)(r + 8) * ldc + c) = make_float2(v2, v3);
                } else if (OMODE == 1) {
                    *(__half2*)(Ch + (long long)r * ldc + c) =
                        __halves2half2(__float2half(v0), __float2half(v1));
                    *(__half2*)(Ch + (long long)(r + 8) * ldc + c) =
                        __halves2half2(__float2half(v2), __float2half(v3));
                } else {
                    // RoPE epilogue: (v0,v1)=(x0,x1) at row r, (v2,v3) at row r+8.
                    // c = h*64 + 2j; identical math to the old rope_q kernel.
                    int hh = c >> 6;
                    int j  = (c & 63) >> 1;
                    float invf = powf(10000.0f, -(float)(2 * j) / (float)ROPE_D);
                    {
                        float p  = (float)pos[r];
                        float an = p * invf;
                        float cs = cosf(an), sn = sinf(an);
                        __half* o = ropeDst + ((size_t)hh * S_LEN + r) * CDIM + KV_LORA;
                        o[j]                = __float2half(v0 * cs - v1 * sn);
                        o[j + ROPE_D / 2]   = __float2half(v1 * cs + v0 * sn);
                    }
                    {
                        float p  = (float)pos[r + 8];
                        float an = p * invf;
                        float cs = cosf(an), sn = sinf(an);
                        __half* o = ropeDst + ((size_t)hh * S_LEN + r + 8) * CDIM + KV_LORA;
                        o[j]                = __float2half(v2 * cs - v3 * sn);
                        o[j + ROPE_D / 2]   = __float2half(v3 * cs + v2 * sn);
                    }
                }
            }
        }
    }
}

// ---------------- fused flash attention (unchanged from R13) ----------------
#define FL_SMEM 200704

__global__ void __launch_bounds__(256, 1)
flash_kernel(const __half* __restrict__ Qf, const __half* __restrict__ Kf,
             const __half* __restrict__ Vk, __half* __restrict__ attn,
             float scale)
{
    extern __shared__ char smem[];
    const int i = 15 - blockIdx.x;
    const int h = blockIdx.z;
    const int row0 = i * 128;
    const __half* Q = Qf + (size_t)h * S_LEN * CDIM;
    const __half* V = Vk + (size_t)h * S_LEN * V_D;
    const float scale2 = scale * 1.44269504088896f;

    const int tid  = threadIdx.x;
    const int lane = tid & 31;
    const int wid  = tid >> 5;
    const int wm   = wid >> 2;
    const int wn   = wid & 3;
    const int g    = lane >> 2;
    const int tig  = lane & 3;

    uint32_t sb = smem_addr32(smem);
    uint32_t Pb = sb + 98304u;
    uint32_t Vb = sb + 131072u;
    float* smax = (float*)(smem + 196608);
    float* ssum = (float*)(smem + 198656);

    float O[4][4][4] = {};
    float mst[4][2], lst[4][2];
    #pragma unroll
    for (int mi = 0; mi < 4; mi++) { mst[mi][0] = mst[mi][1] = -1e30f; lst[mi][0] = lst[mi][1] = 0.f; }

    const int rbA  = wm * 64 + ((lane >> 3) & 1) * 8 + (lane & 7);
    const int ksel = lane >> 4;

    auto issueV = [&](int jj) {
        uint32_t vb = Vb + (uint32_t)((jj & 1) * 32768);
        #pragma unroll
        for (int e = 0; e < 8; e++) {
            int id = tid + e * 256;
            int k = id >> 4, c = id & 15;
            uint32_t dst = vb + (uint32_t)((k >> 6) * 16384 + (k & 63) * 256 + ((c ^ (k & 7)) << 4));
            cpasync16(dst, V + (size_t)(jj * 128 + k) * V_D + c * 8, 16);
        }
        cp_commit();
    };
    auto issueS = [&](int jj, int t) {
        int k0 = t << 6;
        uint32_t st = sb + (uint32_t)((t % 3) * STG_BYTES);
        #pragma unroll
        for (int e = 0; e < 4; e++) {
            int id = tid + e * 256;
            int r = id >> 3, c = id & 7;
            cpasync16(st + (uint32_t)(r * 128 + ((c ^ (r & 7)) * 16)),
                      Q + (size_t)(row0 + r) * CDIM + k0 + c * 8, 16);
        }
        #pragma unroll
        for (int e = 0; e < 4; e++) {
            int id = tid + e * 256;
            int n = id >> 3, c = id & 7;
            cpasync16(st + 16384u + (uint32_t)(n * 128 + ((c ^ (n & 7)) * 16)),
                      Kf + (size_t)(jj * 128 + n) * CDIM + k0 + c * 8, 16);
        }
        cp_commit();
    };

    issueV(0);
    issueS(0, 0);
    issueS(0, 1);

    for (int j = 0; j <= i; j++) {
        float S[4][4][4] = {};
        for (int t = 0; t < 9; t++) {
            if (t + 1 < 9) cp_wait<1>();
            else           cp_wait<0>();
            __syncthreads();
            if (t + 2 < 9) issueS(j, t + 2);

            uint32_t stA = sb + (uint32_t)((t % 3) * STG_BYTES);
            uint32_t stB = stA + 16384u;
            #pragma unroll
            for (int kk16 = 0; kk16 < 4; kk16++) {
                unsigned af[4][4], bf[4][2];
                int cA = kk16 * 2 + ksel;
                #pragma unroll
                for (int mi = 0; mi < 4; mi++) {
                    int r = rbA + mi * 16;
                    ldsm4(af[mi][0], af[mi][1], af[mi][2], af[mi][3],
                          stA + (uint32_t)(r * 128 + ((cA ^ (r & 7)) << 4)));
                }
                int cB = kk16 * 2 + ((lane >> 3) & 1);
                #pragma unroll
                for (int njp = 0; njp < 2; njp++) {
                    int n = wn * 32 + njp * 16 + (lane >> 4) * 8 + (lane & 7);
                    ldsm4(bf[2 * njp][0], bf[2 * njp][1], bf[2 * njp + 1][0], bf[2 * njp + 1][1],
                          stB + (uint32_t)(n * 128 + ((cB ^ (n & 7)) << 4)));
                }
                #pragma unroll
                for (int mi = 0; mi < 4; mi++)
                    #pragma unroll
                    for (int nj = 0; nj < 4; nj++)
                        mma16(S[mi][nj], af[mi], bf[nj]);
            }
        }

        const bool diag = (j == i);
        float lm[4][2];
        #pragma unroll
        for (int mi = 0; mi < 4; mi++) { lm[mi][0] = lm[mi][1] = -1e30f; }
        #pragma unroll
        for (int mi = 0; mi < 4; mi++)
            #pragma unroll
            for (int nj = 0; nj < 4; nj++)
                #pragma unroll
                for (int c = 0; c < 4; c++) {
                    int hf = c >> 1;
                    int rl = wm * 64 + mi * 16 + g + hf * 8;
                    int cl = wn * 32 + nj * 8 + tig * 2 + (c & 1);
                    float s = S[mi][nj][c] * scale2;
                    if (diag && cl > rl) s = -1e30f;
                    S[mi][nj][c] = s;
                    lm[mi][hf] = fmaxf(lm[mi][hf], s);
                }
        #pragma unroll
        for (int mi = 0; mi < 4; mi++)
            #pragma unroll
            for (int hf = 0; hf < 2; hf++) {
                lm[mi][hf] = fmaxf(lm[mi][hf], __shfl_xor_sync(0xffffffffu, lm[mi][hf], 1));
                lm[mi][hf] = fmaxf(lm[mi][hf], __shfl_xor_sync(0xffffffffu, lm[mi][hf], 2));
            }
        if (tig == 0) {
            #pragma unroll
            for (int mi = 0; mi < 4; mi++)
                #pragma unroll
                for (int hf = 0; hf < 2; hf++)
                    smax[wn * 128 + wm * 64 + mi * 16 + g + hf * 8] = lm[mi][hf];
        }
        __syncthreads();

        float alpha_[4][2];
        #pragma unroll
        for (int mi = 0; mi < 4; mi++)
            #pragma unroll
            for (int hf = 0; hf < 2; hf++) {
                int rl = wm * 64 + mi * 16 + g + hf * 8;
                float mj = fmaxf(fmaxf(smax[rl], smax[128 + rl]),
                                 fmaxf(smax[256 + rl], smax[384 + rl]));
                float mn = fmaxf(mst[mi][hf], mj);
                float al = ex2f(mst[mi][hf] - mn);
                mst[mi][hf] = mn;
                lst[mi][hf] *= al;
                alpha_[mi][hf] = al;
            }
        #pragma unroll
        for (int mi = 0; mi < 4; mi++)
            #pragma unroll
            for (int nj = 0; nj < 4; nj++) {
                O[mi][nj][0] *= alpha_[mi][0]; O[mi][nj][1] *= alpha_[mi][0];
                O[mi][nj][2] *= alpha_[mi][1]; O[mi][nj][3] *= alpha_[mi][1];
            }

        float ls[4][2];
        #pragma unroll
        for (int mi = 0; mi < 4; mi++) { ls[mi][0] = ls[mi][1] = 0.f; }
        #pragma unroll
        for (int mi = 0; mi < 4; mi++)
            #pragma unroll
            for (int nj = 0; nj < 4; nj++) {
                #pragma unroll
                for (int c = 0; c < 4; c++) {
                    int hf = c >> 1;
                    float p = ex2f(S[mi][nj][c] - mst[mi][hf]);
                    S[mi][nj][c] = p;
                    ls[mi][hf] += p;
                }
                int cc = wn * 32 + nj * 8 + tig * 2;
                uint32_t hb  = (uint32_t)(cc >> 6) * 16384u;
                int ccc = cc & 63;
                int r1 = wm * 64 + mi * 16 + g;
                uint32_t a1 = Pb + hb + (uint32_t)(r1 * 128 + ((((ccc >> 3) ^ (r1 & 7))) << 4) + (ccc & 7) * 2);
                int r2 = r1 + 8;
                uint32_t a2 = Pb + hb + (uint32_t)(r2 * 128 + ((((ccc >> 3) ^ (r2 & 7))) << 4) + (ccc & 7) * 2);
                __half2 v1 = __floats2half2_rn(S[mi][nj][0] * 512.f, S[mi][nj][1] * 512.f);
                __half2 v2 = __floats2half2_rn(S[mi][nj][2] * 512.f, S[mi][nj][3] * 512.f);
                *(__half2*)(smem + (a1 - sb)) = v1;
                *(__half2*)(smem + (a2 - sb)) = v2;
            }
        #pragma unroll
        for (int mi = 0; mi < 4; mi++)
            #pragma unroll
            for (int hf = 0; hf < 2; hf++) {
                ls[mi][hf] += __shfl_xor_sync(0xffffffffu, ls[mi][hf], 1);
                ls[mi][hf] += __shfl_xor_sync(0xffffffffu, ls[mi][hf], 2);
            }
        if (tig == 0) {
            #pragma unroll
            for (int mi = 0; mi < 4; mi++)
                #pragma unroll
                for (int hf = 0; hf < 2; hf++)
                    ssum[wn * 128 + wm * 64 + mi * 16 + g + hf * 8] = ls[mi][hf];
        }
        __syncthreads();

        #pragma unroll
        for (int mi = 0; mi < 4; mi++)
            #pragma unroll
            for (int hf = 0; hf < 2; hf++) {
                int rl = wm * 64 + mi * 16 + g + hf * 8;
                lst[mi][hf] += ssum[rl] + ssum[128 + rl] + ssum[256 + rl] + ssum[384 + rl];
            }

        if (j < i) {
            issueV(j + 1);
            issueS(j + 1, 0);
            issueS(j + 1, 1);
        }

        uint32_t Vcur = Vb + (uint32_t)((j & 1) * 32768);
        #pragma unroll
        for (int kk64 = 0; kk64 < 2; kk64++) {
            uint32_t stA = Pb + (uint32_t)(kk64 * 16384);
            uint32_t stV = Vcur + (uint32_t)(kk64 * 16384);
            #pragma unroll
            for (int kk16 = 0; kk16 < 4; kk16++) {
                unsigned af[4][4], bf[4][2];
                int cA = kk16 * 2 + ksel;
                #pragma unroll
                for (int mi = 0; mi < 4; mi++) {
                    int r = rbA + mi * 16;
                    ldsm4(af[mi][0], af[mi][1], af[mi][2], af[mi][3],
                          stA + (uint32_t)(r * 128 + ((cA ^ (r & 7)) << 4)));
                }
                int kr = kk16 * 16 + ((lane >> 3) & 1) * 8 + (lane & 7);
                #pragma unroll
                for (int njp = 0; njp < 2; njp++) {
                    int nch = wn * 4 + njp * 2 + (lane >> 4);
                    ldsm4t(bf[2 * njp][0], bf[2 * njp][1], bf[2 * njp + 1][0], bf[2 * njp + 1][1],
                           stV + (uint32_t)(kr * 256 + ((nch ^ (kr & 7)) << 4)));
                }
                #pragma unroll
                for (int mi = 0; mi < 4; mi++)
                    #pragma unroll
                    for (int nj = 0; nj < 4; nj++)
                        mma16(O[mi][nj], af[mi], bf[nj]);
            }
        }
    }

    #pragma unroll
    for (int mi = 0; mi < 4; mi++) {
        float inv0 = 1.0f / (512.0f * lst[mi][0]);
        float inv1 = 1.0f / (512.0f * lst[mi][1]);
        int r = row0 + wm * 64 + mi * 16 + g;
        #pragma unroll
        for (int nj = 0; nj < 4; nj++) {
            int c = h * V_D + wn * 32 + nj * 8 + tig * 2;
            *(__half2*)(attn + (size_t)r * (NH * V_D) + c) =
                __floats2half2_rn(O[mi][nj][0] * inv0, O[mi][nj][1] * inv0);
            *(__half2*)(attn + (size_t)(r + 8) * (NH * V_D) + c) =
                __floats2half2_rn(O[mi][nj][2] * inv1, O[mi][nj][3] * inv1);
        }
    }
}

// ---------------- prepass converts (one uint4 per thread, full grid) ----------------
__global__ void convert_f2h_kernel(const float4* __restrict__ src, uint4* __restrict__ dst, int n8)
{
    int i = blockIdx.x * blockDim.x + threadIdx.x;
    if (i < n8) {
        float4 a = src[2 * i], b = src[2 * i + 1];
        __half2 h0 = __floats2half2_rn(a.x, a.y);
        __half2 h1 = __floats2half2_rn(a.z, a.w);
        __half2 h2 = __floats2half2_rn(b.x, b.y);
        __half2 h3 = __floats2half2_rn(b.z, b.w);
        uint4 o;
        o.x = *(unsigned*)&h0; o.y = *(unsigned*)&h1;
        o.z = *(unsigned*)&h2; o.w = *(unsigned*)&h3;
        dst[i] = o;
    }
}
__global__ void pack_f2h_kernel(const float* __restrict__ src, __half* __restrict__ dst,
                                int C, int ldd, int off)
{
    int c4 = blockIdx.x * blockDim.x + threadIdx.x;
    int r  = blockIdx.y;
    if (c4 < C / 4) {
        float4 v = *(const float4*)(src + (long long)r * C + 4 * c4);
        __half2 h0 = __floats2half2_rn(v.x, v.y);
        __half2 h1 = __floats2half2_rn(v.z, v.w);
        uint2 o; o.x = *(unsigned*)&h0; o.y = *(unsigned*)&h1;
        *(uint2*)(dst + (long long)r * ldd + off + 4 * c4) = o;
    }
}

// ---------------- rmsnorm kernels (unchanged) ----------------
__global__ void kva_rms_rope_kernel(const float* __restrict__ pre12,
                                    const float* __restrict__ kv_ln,
                                    const int*   __restrict__ pos_ids,
                                    __half* __restrict__ kfull)
{
    int s = blockIdx.x;
    const float* x = pre12 + (long long)s * N12 + Q_LORA;
    __half* out = kfull + (long long)s * CDIM;

    __shared__ float red[128];
    float ss = 0.0f;
    for (int i = threadIdx.x; i < KV_LORA; i += 128) { float v = x[i]; ss += v * v; }
    red[threadIdx.x] = ss; __syncthreads();
    for (int st = 64; st > 0; st >>= 1) {
        if (threadIdx.x < st) red[threadIdx.x] += red[threadIdx.x + st];
        __syncthreads();
    }
    float scale = rsqrtf(red[0] / (float)KV_LORA + 1e-6f);

    for (int i = threadIdx.x; i < KV_LORA; i += 128)
        out[i] = __float2half(x[i] * scale * kv_ln[i]);

    if (threadIdx.x < ROPE_D / 2) {
        int j = threadIdx.x;
        float pos  = (float)pos_ids[s];
        float invf = powf(10000.0f, -(float)(2 * j) / (float)ROPE_D);
        float ang  = pos * invf;
        float c = cosf(ang), sn = sinf(ang);
        float x0 = x[KV_LORA + 2 * j];
        float x1 = x[KV_LORA + 2 * j + 1];
        out[KV_LORA + j]              = __float2half(x0 * c - x1 * sn);
        out[KV_LORA + ROPE_D / 2 + j] = __float2half(x1 * c + x0 * sn);
    }
}
__global__ void qa_rms_kernel(const float* __restrict__ pre12,
                              const float* __restrict__ w,
                              __half* __restrict__ outp)
{
    int s = blockIdx.x;
    const float* x = pre12 + (long long)s * N12;
    __half* o = outp + (long long)s * Q_LORA;

    __shared__ float red[256];
    float ss = 0.0f;
    for (int i = threadIdx.x; i < Q_LORA; i += 256) { float v = x[i]; ss += v * v; }
    red[threadIdx.x] = ss; __syncthreads();
    for (int st = 128; st > 0; st >>= 1) {
        if (threadIdx.x < st) red[threadIdx.x] += red[threadIdx.x + st];
        __syncthreads();
    }
    float scale = rsqrtf(red[0] / (float)Q_LORA + 1e-6f);
    for (int i = threadIdx.x; i < Q_LORA; i += 256)
        o[i] = __float2half(x[i] * scale * w[i]);
}

// ---------------- host launchers ----------------
template<int OMODE>
static void launch_gemm16(const __half* A, const __half* B, void* C,
                          int M, int N, int K, int lda, int ldb, int ldc,
                          long long sA, long long sB, long long sC,
                          int batch, float alpha,
                          const int* pos = nullptr, __half* ropeDst = nullptr)
{
    dim3 grid(M / 128, (N + 127) / 128, batch);
    cudaFuncSetAttribute(gemm16_kernel<OMODE>, cudaFuncAttributeMaxDynamicSharedMemorySize, 3 * STG_BYTES);
    gemm16_kernel<OMODE><<<grid, 256, 3 * STG_BYTES>>>(A, B, C, M, N, K, lda, ldb, ldc,
                                                       sA, sB, sC, alpha, pos, ropeDst);
}
static void launch_convert(const float* src, __half* dst, size_t n)
{
    int n8 = (int)(n / 8);
    int blocks = (n8 + 255) / 256;
    convert_f2h_kernel<<<blocks, 256>>>((const float4*)src, (uint4*)dst, n8);
}

extern "C" void kernel_launch(void* const* d_in, const int* in_sizes, int n_in,
                              void* d_out, int out_size)
{
    (void)in_sizes; (void)n_in; (void)out_size;
    const float* X        = (const float*)d_in[0];
    const int*   pos      = (const int*)d_in[2];
    const float* W_kv_a   = (const float*)d_in[3];
    const float* W_q_a    = (const float*)d_in[4];
    const float* q_ln     = (const float*)d_in[5];
    const float* kv_ln    = (const float*)d_in[6];
    const float* q_rope_w = (const float*)d_in[7];
    const float* fusedqk  = (const float*)d_in[8];
    const float* v_up     = (const float*)d_in[9];
    const float* W_o      = (const float*)d_in[10];
    float* out = (float*)d_out;

    float  *pre12;
    __half *xh, *qah, *kfullh, *qfullh, *vkva, *attnh;
    __half *w12h, *qrwh, *fqkh, *vuph, *woh;
    cudaGetSymbolAddress((void**)&pre12,  g_pre12);
    cudaGetSymbolAddress((void**)&xh,     g_xh);
    cudaGetSymbolAddress((void**)&qah,    g_qah);
    cudaGetSymbolAddress((void**)&kfullh, g_kfullh);
    cudaGetSymbolAddress((void**)&qfullh, g_qfullh);
    cudaGetSymbolAddress((void**)&vkva,   g_vkva);
    cudaGetSymbolAddress((void**)&attnh,  g_attnh);
    cudaGetSymbolAddress((void**)&w12h,   g_w12h);
    cudaGetSymbolAddress((void**)&qrwh,   g_qrwh);
    cudaGetSymbolAddress((void**)&fqkh,   g_fqkh);
    cudaGetSymbolAddress((void**)&vuph,   g_vuph);
    cudaGetSymbolAddress((void**)&woh,    g_woh);

    const float scale = 1.0f / sqrtf(192.0f);

    // 0) prepass converts
    launch_convert(X,        xh,   (size_t)S_LEN * HID);
    pack_f2h_kernel<<<dim3((Q_LORA / 4 + 255) / 256, HID), 256>>>(W_q_a,  w12h, Q_LORA, N12, 0);
    pack_f2h_kernel<<<dim3((CDIM   / 4 + 255) / 256, HID), 256>>>(W_kv_a, w12h, CDIM,   N12, Q_LORA);
    launch_convert(q_rope_w, qrwh, (size_t)Q_LORA * (NH * ROPE_D));
    launch_convert(fusedqk,  fqkh, (size_t)NH * Q_LORA * KV_LORA);
    launch_convert(v_up,     vuph, (size_t)NH * KV_LORA * V_D);
    launch_convert(W_o,      woh,  (size_t)(NH * V_D) * HID);

    // 1+2) pre12 = X @ [W_q | W_kv]   [S,2112] f32
    launch_gemm16<0>(xh, w12h, pre12, S_LEN, N12, HID,
                     HID, N12, N12, 0, 0, 0, 1, 1.0f);
    // 3) kfullh
    kva_rms_rope_kernel<<<S_LEN, 128>>>(pre12, kv_ln, pos, kfullh);
    // 3b) vkva[h] = kva @ v_up[h]
    launch_gemm16<1>(kfullh, vuph, vkva, S_LEN, V_D, KV_LORA,
                     CDIM, V_D, V_D,
                     0, (long long)KV_LORA * V_D, (long long)S_LEN * V_D,
                     NH, 1.0f);
    // 4) qah
    qa_rms_kernel<<<S_LEN, 256>>>(pre12, q_ln, qah);
    // 5+6) qpe GEMM with fused RoPE epilogue -> qfullh rope columns
    launch_gemm16<2>(qah, qrwh, nullptr, S_LEN, NH * ROPE_D, Q_LORA,
                     Q_LORA, NH * ROPE_D, 0, 0, 0, 0, 1, 1.0f, pos, qfullh);
    // 7) dq = qa @ fusedqk[h] -> qfullh[:, :512]
    launch_gemm16<1>(qah, fqkh, qfullh, S_LEN, KV_LORA, Q_LORA,
                     Q_LORA, KV_LORA, CDIM,
                     0, (long long)Q_LORA * KV_LORA, (long long)S_LEN * CDIM,
                     NH, 1.0f);
    // 8-10) fused flash attention -> attnh
    {
        cudaFuncSetAttribute(flash_kernel, cudaFuncAttributeMaxDynamicSharedMemorySize, FL_SMEM);
        dim3 grid(S_LEN / 128, 1, NH);
        flash_kernel<<<grid, 256, FL_SMEM>>>(qfullh, kfullh, vkva, attnh, scale);
    }
    // 12) out = attn @ W_o
    launch_gemm16<0>(attnh, woh, out, S_LEN, HID, NH * V_D,
                     NH * V_D, HID, HID, 0, 0, 0, 1, 1.0f);
}